// round 11
// baseline (speedup 1.0000x reference)
#include <cuda_runtime.h>
#include <cuda_bf16.h>
#include <cstddef>

// Problem shape (fixed per reference): feats [B, C, H, W] fp32, R [H, C, C] fp32.
#define Bn 16
#define Cn 256
#define Hn 128
#define Wn 128
#define Kn (Cn / 2)   // 128 channel pairs

// 256-bit global load/store (sm_100+: LDG.E.256 / STG.E.256), streaming hint.
struct f8 { float v[8]; };

__device__ __forceinline__ f8 ldg256_cs(const float* p) {
    f8 r;
    asm volatile("ld.global.cs.v8.f32 {%0,%1,%2,%3,%4,%5,%6,%7}, [%8];"
                 : "=f"(r.v[0]), "=f"(r.v[1]), "=f"(r.v[2]), "=f"(r.v[3]),
                   "=f"(r.v[4]), "=f"(r.v[5]), "=f"(r.v[6]), "=f"(r.v[7])
                 : "l"(p));
    return r;
}

__device__ __forceinline__ void stg256_cs(float* p, const f8& r) {
    asm volatile("st.global.cs.v8.f32 [%0], {%1,%2,%3,%4,%5,%6,%7,%8};"
                 :: "l"(p),
                    "f"(r.v[0]), "f"(r.v[1]), "f"(r.v[2]), "f"(r.v[3]),
                    "f"(r.v[4]), "f"(r.v[5]), "f"(r.v[6]), "f"(r.v[7])
                 : "memory");
}

// Fused streaming rotation with 256-bit accesses.
// One thread = (b, k, h, w8): reads 32B from the even channel row and 32B from
// the odd channel row (64KB apart), rotates, writes both. Low 4 bits = w8 so
// each half-warp covers one contiguous 512B row (perfectly coalesced);
// cos/sin fetch from R is half-warp-uniform (2 sectors per warp, L2-cached
// across the 16 batches sharing each (h,k)).
__global__ void __launch_bounds__(256) rope_rotate_v8_kernel(
    const float* __restrict__ f,
    const float* __restrict__ R,
    float* __restrict__ out) {
    unsigned tid = blockIdx.x * blockDim.x + threadIdx.x;
    unsigned w8 = tid & 15u;            // W/8 = 16
    unsigned h  = (tid >> 4) & 127u;    // Hn
    unsigned k  = (tid >> 11) & 127u;   // Kn
    unsigned b  = tid >> 18;            // Bn

    // 2x2 block extraction from the dense rotation matrix:
    //   cos = R[h, 2k, 2k],  sin = R[h, 2k+1, 2k]
    const float* Rh = R + (size_t)h * (Cn * Cn) + (size_t)(2u * k) * Cn + 2u * k;
    float cosv = __ldg(Rh);
    float sinv = __ldg(Rh + Cn);

    size_t base = ((((size_t)b * Cn + 2u * k) * Hn + h) * Wn) + 8u * w8;
    const size_t chan = (size_t)Hn * Wn;   // odd-channel offset

    f8 e = ldg256_cs(f + base);
    f8 o = ldg256_cs(f + base + chan);

    f8 re, ro;
#pragma unroll
    for (int i = 0; i < 8; i++) {
        re.v[i] = cosv * e.v[i] - sinv * o.v[i];
        ro.v[i] = sinv * e.v[i] + cosv * o.v[i];
    }

    stg256_cs(out + base, re);
    stg256_cs(out + base + chan, ro);
}

extern "C" void kernel_launch(void* const* d_in, const int* in_sizes, int n_in,
                              void* d_out, int out_size) {
    const float* feats = (const float*)d_in[0];   // [16, 256, 128, 128]
    const float* rota  = (const float*)d_in[1];   // [128, 256, 256]
    float* out = (float*)d_out;                   // [16, 256, 128, 128]
    (void)in_sizes; (void)n_in; (void)out_size;

    // Single fused launch: Bn*Kn*Hn*(Wn/8) = 4,194,304 threads.
    const unsigned total = Bn * Kn * Hn * (Wn / 8);
    rope_rotate_v8_kernel<<<total / 256, 256>>>(feats, rota, out);
}

// round 12
// speedup vs baseline: 1.0379x; 1.0379x over previous
#include <cuda_runtime.h>
#include <cuda_bf16.h>
#include <cstddef>

// Problem shape (fixed per reference): feats [B, C, H, W] fp32, R [H, C, C] fp32.
#define Bn 16
#define Cn 256
#define Hn 128
#define Wn 128
#define Kn (Cn / 2)   // 128 channel pairs

// Fused streaming rotation (best-known R5 mapping, 512-thread blocks).
// One thread = one (b, k, h, w4) tile. Low 5 bits = w4, so within a warp
// (b, k, h) are fixed:
//   -> cos/sin loads from R are warp-uniform (1 sector, broadcast),
//      L2-cached across the 16 batches that share each (h, k).
//   reads  float4 even = feats[b, 2k,   h, 4*w4 .. +3]
//          float4 odd  = feats[b, 2k+1, h, 4*w4 .. +3]
//   writes the rotated pair to the same locations in out.
// feats/out have zero reuse -> streaming hints (__ldcs/__stcs) keep them
// from evicting the R-diagonal lines in L2.
__global__ void __launch_bounds__(512) rope_rotate_fused_kernel(
    const float* __restrict__ f,
    const float* __restrict__ R,
    float* __restrict__ out) {
    unsigned tid = blockIdx.x * blockDim.x + threadIdx.x;
    unsigned w4 = tid & 31u;            // W/4 = 32
    unsigned h  = (tid >> 5) & 127u;    // Hn
    unsigned k  = (tid >> 12) & 127u;   // Kn
    unsigned b  = tid >> 19;            // Bn

    // Warp-uniform 2x2 block extraction from the dense rotation matrix:
    //   cos = R[h, 2k,   2k]
    //   sin = R[h, 2k+1, 2k]   (the +sin entry; c even column)
    const float* Rh = R + (size_t)h * (Cn * Cn) + (size_t)(2u * k) * Cn + 2u * k;
    float cosv = __ldg(Rh);
    float sinv = __ldg(Rh + Cn);

    size_t base = ((((size_t)b * Cn + 2u * k) * Hn + h) * Wn) + 4u * w4;
    const float4 e = __ldcs(reinterpret_cast<const float4*>(f + base));
    const float4 o = __ldcs(reinterpret_cast<const float4*>(f + base + (size_t)Hn * Wn));

    float4 re, ro;
    re.x = cosv * e.x - sinv * o.x;  ro.x = sinv * e.x + cosv * o.x;
    re.y = cosv * e.y - sinv * o.y;  ro.y = sinv * e.y + cosv * o.y;
    re.z = cosv * e.z - sinv * o.z;  ro.z = sinv * e.z + cosv * o.z;
    re.w = cosv * e.w - sinv * o.w;  ro.w = sinv * e.w + cosv * o.w;

    __stcs(reinterpret_cast<float4*>(out + base), re);
    __stcs(reinterpret_cast<float4*>(out + base + (size_t)Hn * Wn), ro);
}

extern "C" void kernel_launch(void* const* d_in, const int* in_sizes, int n_in,
                              void* d_out, int out_size) {
    const float* feats = (const float*)d_in[0];   // [16, 256, 128, 128]
    const float* rota  = (const float*)d_in[1];   // [128, 256, 256]
    float* out = (float*)d_out;                   // [16, 256, 128, 128]
    (void)in_sizes; (void)n_in; (void)out_size;

    // Single fused launch: Bn*Kn*Hn*(Wn/4) = 16,777,216 threads, 512/block.
    const unsigned total = Bn * Kn * Hn * (Wn / 4);
    rope_rotate_fused_kernel<<<total / 512, 512>>>(feats, rota, out);
}

// round 17
// speedup vs baseline: 1.0470x; 1.0088x over previous
#include <cuda_runtime.h>
#include <cuda_bf16.h>
#include <cstddef>

// Problem shape (fixed per reference): feats [B, C, H, W] fp32, R [H, C, C] fp32.
#define Bn 16
#define Cn 256
#define Hn 128
#define Wn 128
#define Kn (Cn / 2)   // 128 channel pairs

// Fused streaming rotation (best-known R5 mapping, 1024-thread blocks).
// One thread = one (b, k, h, w4) tile. Low 5 bits = w4, so within a warp
// (b, k, h) are fixed:
//   -> cos/sin loads from R are warp-uniform (1 sector, broadcast),
//      L2-cached across the 16 batches that share each (h, k).
//   reads  float4 even = feats[b, 2k,   h, 4*w4 .. +3]
//          float4 odd  = feats[b, 2k+1, h, 4*w4 .. +3]
//   writes the rotated pair to the same locations in out.
// feats/out have zero reuse -> streaming hints (__ldcs/__stcs) keep them
// from evicting the R-diagonal lines in L2.
__global__ void __launch_bounds__(1024) rope_rotate_fused_kernel(
    const float* __restrict__ f,
    const float* __restrict__ R,
    float* __restrict__ out) {
    unsigned tid = blockIdx.x * blockDim.x + threadIdx.x;
    unsigned w4 = tid & 31u;            // W/4 = 32
    unsigned h  = (tid >> 5) & 127u;    // Hn
    unsigned k  = (tid >> 12) & 127u;   // Kn
    unsigned b  = tid >> 19;            // Bn

    // Warp-uniform 2x2 block extraction from the dense rotation matrix:
    //   cos = R[h, 2k,   2k]
    //   sin = R[h, 2k+1, 2k]   (the +sin entry; c even column)
    const float* Rh = R + (size_t)h * (Cn * Cn) + (size_t)(2u * k) * Cn + 2u * k;
    float cosv = __ldg(Rh);
    float sinv = __ldg(Rh + Cn);

    size_t base = ((((size_t)b * Cn + 2u * k) * Hn + h) * Wn) + 4u * w4;
    const float4 e = __ldcs(reinterpret_cast<const float4*>(f + base));
    const float4 o = __ldcs(reinterpret_cast<const float4*>(f + base + (size_t)Hn * Wn));

    float4 re, ro;
    re.x = cosv * e.x - sinv * o.x;  ro.x = sinv * e.x + cosv * o.x;
    re.y = cosv * e.y - sinv * o.y;  ro.y = sinv * e.y + cosv * o.y;
    re.z = cosv * e.z - sinv * o.z;  ro.z = sinv * e.z + cosv * o.z;
    re.w = cosv * e.w - sinv * o.w;  ro.w = sinv * e.w + cosv * o.w;

    __stcs(reinterpret_cast<float4*>(out + base), re);
    __stcs(reinterpret_cast<float4*>(out + base + (size_t)Hn * Wn), ro);
}

extern "C" void kernel_launch(void* const* d_in, const int* in_sizes, int n_in,
                              void* d_out, int out_size) {
    const float* feats = (const float*)d_in[0];   // [16, 256, 128, 128]
    const float* rota  = (const float*)d_in[1];   // [128, 256, 256]
    float* out = (float*)d_out;                   // [16, 256, 128, 128]
    (void)in_sizes; (void)n_in; (void)out_size;

    // Single fused launch: Bn*Kn*Hn*(Wn/4) = 16,777,216 threads, 1024/block.
    const unsigned total = Bn * Kn * Hn * (Wn / 4);
    rope_rotate_fused_kernel<<<total / 1024, 1024>>>(feats, rota, out);
}